// round 8
// baseline (speedup 1.0000x reference)
#include <cuda_runtime.h>
#include <cuda_bf16.h>

#define B_   4
#define C_   64
#define O_   64
#define H_   128
#define W_   128
#define KK   9
#define HW_  (H_ * W_)

// ---------------- device scratch (allocation-free rule) ----------------
__device__ float4 g_x4[B_ * C_ * HW_];   // (x[y][x], x[y][x+1], x[y+1][x], x[y+1][x+1])
__device__ uint2  g_wB[KK * 2 * 8 * 8 * 32];  // [k][plane][kt][nt][lane] -> (b0,b1)

// ---------------- prep kernels ----------------
__global__ void prep_w(const float* __restrict__ w) {
    int i = blockIdx.x * 256 + threadIdx.x;          // over O*C*KK = 36864
    if (i < O_ * C_ * KK) {
        int o = i / (C_ * KK);
        int r = i - o * (C_ * KK);
        int c = r / KK;
        int k = r - c * KK;
        float v = w[i];
        unsigned hb = __float_as_uint(v) & 0xFFFF0000u;       // bf16 truncation
        float lf = v - __uint_as_float(hb);
        unsigned h16 = hb >> 16;
        unsigned l16 = (unsigned)__bfloat16_as_ushort(__float2bfloat16(lf));
        unsigned hword = h16 | (h16 << 16);                    // (wh, wh) k-pair
        unsigned lword = l16 | (l16 << 16);                    // (wl, wl) k-pair
        int kt = c >> 3, cl = c & 7;
        int j  = cl >> 2, tg = cl & 3;
        int nt = o >> 3;
        int lane = ((o & 7) << 2) | tg;
        unsigned* bh = (unsigned*)&g_wB[(((k * 2 + 0) * 8 + kt) * 8 + nt) * 32 + lane];
        unsigned* bl = (unsigned*)&g_wB[(((k * 2 + 1) * 8 + kt) * 8 + nt) * 32 + lane];
        bh[j] = hword;
        bl[j] = lword;
    }
}

__global__ void prep_x4(const float* __restrict__ x) {
    int i = blockIdx.x * 256 + threadIdx.x;          // over B*C*HW
    if (i < B_ * C_ * HW_) {
        int col = i & (W_ - 1);
        int y   = (i >> 7) & (H_ - 1);
        float a = x[i];
        float b = (col < W_ - 1) ? x[i + 1] : a;
        float c, d;
        if (y < H_ - 1) {
            c = x[i + W_];
            d = (col < W_ - 1) ? x[i + W_ + 1] : c;
        } else { c = a; d = b; }
        g_x4[i] = make_float4(a, b, c, d);
    }
}

// ---------------- main kernel ----------------
// 512 blocks (batch*row), 384 threads: warps 0-7 producers, warps 8-11 MMA consumers.
// smem: A tiles double-buffered: [2][128 px][128 k' bf16] = 2 * 32KB = 64KB
//       row = 256B = 16 units of 16B; unit u stored at u ^ (px & 7)  (XOR swizzle)
#define A_BUF_BYTES 32768
#define SMEM_TOTAL  (2 * A_BUF_BYTES)

#define BSYNC(id)   asm volatile("bar.sync %0, 384;"   :: "r"(id) : "memory")
#define BARRIVE(id) asm volatile("bar.arrive %0, 384;" :: "r"(id) : "memory")

#define LDMX4(r0, r1, r2, r3, addr)                                          \
    asm volatile("ldmatrix.sync.aligned.m8n8.x4.shared.b16 {%0,%1,%2,%3}, [%4];" \
        : "=r"(r0), "=r"(r1), "=r"(r2), "=r"(r3) : "r"(addr))

#define MMA_BF16(d, a0, a1, a2, a3, b0, b1)                                  \
    asm volatile("mma.sync.aligned.m16n8k16.row.col.f32.bf16.bf16.f32 "      \
        "{%0,%1,%2,%3}, {%4,%5,%6,%7}, {%8,%9}, {%0,%1,%2,%3};"              \
        : "+f"((d)[0]), "+f"((d)[1]), "+f"((d)[2]), "+f"((d)[3])             \
        : "r"(a0), "r"(a1), "r"(a2), "r"(a3), "r"(b0), "r"(b1))

__global__ __launch_bounds__(384, 1)
void dconv_main(const float* __restrict__ offset,
                const float* __restrict__ bias,
                float* __restrict__ out) {
    extern __shared__ char smc[];
    unsigned smb;
    asm("{ .reg .u64 t; cvta.to.shared.u64 t, %1; cvt.u32.u64 %0, t; }"
        : "=r"(smb) : "l"(smc));

    const int tid   = threadIdx.x;
    const int batch = blockIdx.x >> 7;
    const int ho    = blockIdx.x & 127;

    if (tid < 256) {
        // ================= PRODUCERS (warps 0-7) =================
        const int p     = tid & 127;         // pixel in row
        const int chalf = tid >> 7;          // channel half (32 c each)
        const float4* xb4  = g_x4 + (batch * C_ + chalf * 32) * HW_;
        const float*  offb = offset + (batch * 2 * KK) * HW_ + ho * W_ + p;

        float offy[KK], offx[KK];
        #pragma unroll
        for (int k = 0; k < KK; k++) {
            offy[k] = __ldg(offb + (2 * k) * HW_);
            offx[k] = __ldg(offb + (2 * k + 1) * HW_);
        }

        for (int k = 0; k < KK; k++) {
            const int s = k & 1;
            if (k >= 2) BSYNC(3 + s);        // wait stage empty

            // bilinear corner math (proven in R7)
            const int ki = k / 3, kj = k - ki * 3;
            const float py  = offy[k] + (float)(ki - 1 + ho);
            const float pxx = offx[k] + (float)(kj - 1 + p);
            const float y0f = floorf(py), x0f = floorf(pxx);
            const float ly = py - y0f,  lx = pxx - x0f;
            const float hy = 1.f - ly,  hx = 1.f - lx;
            const int y0 = (int)y0f, x0 = (int)x0f;

            int ybase; float w_top, w_bot;
            if (y0 >= 0) {
                ybase = min(y0, H_ - 1);
                w_top = (y0 < H_)     ? hy : 0.f;
                w_bot = (y0 < H_ - 1) ? ly : 0.f;
            } else {
                ybase = 0;
                w_top = (y0 == -1) ? ly : 0.f;
                w_bot = 0.f;
            }
            float wa, wb;
            if (x0 >= 0 && x0 < W_) { wa = hx; wb = (x0 < W_ - 1) ? lx : 0.f; }
            else if (x0 == -1)      { wa = lx; wb = 0.f; }
            else                    { wa = 0.f; wb = 0.f; }
            const int bx = min(max(x0, 0), W_ - 1);

            const float u0 = w_top * wa, u1 = w_top * wb;
            const float u2 = w_bot * wa, u3 = w_bot * wb;

            const float4* q = xb4 + ybase * W_ + bx;
            const unsigned Arow = smb + (unsigned)s * A_BUF_BYTES + (unsigned)(p * 256);
            const unsigned sw3  = (unsigned)(p & 7);

            #pragma unroll
            for (int cg = 0; cg < 8; cg++) {
                unsigned wbuf[4];
                #pragma unroll
                for (int cc = 0; cc < 4; cc++) {
                    const float4 t = __ldg(q + (cg * 4 + cc) * HW_);
                    const float v = u0 * t.x + u1 * t.y + u2 * t.z + u3 * t.w;
                    const unsigned hb = __float_as_uint(v) & 0xFFFF0000u;
                    const float lf = v - __uint_as_float(hb);
                    const unsigned l16 =
                        (unsigned)__bfloat16_as_ushort(__float2bfloat16(lf));
                    wbuf[cc] = (hb >> 16) | (l16 << 16);   // (vh, vl) k'-pair
                }
                const unsigned u = (unsigned)(chalf * 8 + cg);
                const unsigned addr = Arow + ((u ^ sw3) << 4);
                asm volatile("st.shared.v4.b32 [%0], {%1,%2,%3,%4};"
                    :: "r"(addr), "r"(wbuf[0]), "r"(wbuf[1]),
                       "r"(wbuf[2]), "r"(wbuf[3]));
            }

            BARRIVE(1 + s);                  // stage full
        }
    } else {
        // ================= CONSUMERS (warps 8-11) =================
        const int wc   = (tid >> 5) - 8;     // 0..3 -> px block of 32
        const int lane = tid & 31;
        const int pxl  = lane & 15;          // ldmatrix row within 16
        const int usel = lane >> 4;          // ldmatrix k-unit select

        float acc[2][8][4];
        #pragma unroll
        for (int mt = 0; mt < 2; mt++)
            #pragma unroll
            for (int nt = 0; nt < 8; nt++)
                #pragma unroll
                for (int q = 0; q < 4; q++) acc[mt][nt][q] = 0.f;

        for (int k = 0; k < KK; k++) {
            const int s = k & 1;
            BSYNC(1 + s);                    // wait stage full

            const unsigned Abase = smb + (unsigned)s * A_BUF_BYTES;
            const uint2* wB = g_wB + (k * 2) * 8 * 8 * 32 + lane;

            #pragma unroll
            for (int kt = 0; kt < 8; kt++) {
                unsigned a[2][4];
                #pragma unroll
                for (int mt = 0; mt < 2; mt++) {
                    const int px_l = wc * 32 + mt * 16 + pxl;
                    const unsigned u = (unsigned)(2 * kt + usel);
                    const unsigned addr = Abase + (unsigned)(px_l * 256)
                                        + ((u ^ (unsigned)(px_l & 7)) << 4);
                    LDMX4(a[mt][0], a[mt][1], a[mt][2], a[mt][3], addr);
                }
                #pragma unroll
                for (int nt = 0; nt < 8; nt++) {
                    const uint2 bh = __ldg(wB + ((0 * 8 + kt) * 8 + nt) * 32);
                    const uint2 bl = __ldg(wB + ((1 * 8 + kt) * 8 + nt) * 32);
                    MMA_BF16(acc[0][nt], a[0][0], a[0][1], a[0][2], a[0][3],
                             bh.x, bh.y);
                    MMA_BF16(acc[0][nt], a[0][0], a[0][1], a[0][2], a[0][3],
                             bl.x, bl.y);
                    MMA_BF16(acc[1][nt], a[1][0], a[1][1], a[1][2], a[1][3],
                             bh.x, bh.y);
                    MMA_BF16(acc[1][nt], a[1][0], a[1][1], a[1][2], a[1][3],
                             bl.x, bl.y);
                }
            }

            BARRIVE(3 + s);                  // stage empty
        }

        // ---------------- epilogue ----------------
        const int g = lane >> 2, tg = lane & 3;
        #pragma unroll
        for (int nt = 0; nt < 8; nt++) {
            const int o = nt * 8 + 2 * tg;
            const float b0 = __ldg(bias + o);
            const float b1 = __ldg(bias + o + 1);
            float* o0 = out + (batch * O_ + o) * HW_ + ho * W_;
            float* o1 = o0 + HW_;
            #pragma unroll
            for (int mt = 0; mt < 2; mt++) {
                const int wo = wc * 32 + mt * 16 + g;
                o0[wo]     = acc[mt][nt][0] + b0;
                o1[wo]     = acc[mt][nt][1] + b1;
                o0[wo + 8] = acc[mt][nt][2] + b0;
                o1[wo + 8] = acc[mt][nt][3] + b1;
            }
        }
    }
}

extern "C" void kernel_launch(void* const* d_in, const int* in_sizes, int n_in,
                              void* d_out, int out_size) {
    const float* x      = (const float*)d_in[0];
    const float* offset = (const float*)d_in[1];
    const float* weight = (const float*)d_in[2];
    const float* bias   = (const float*)d_in[3];
    float* out = (float*)d_out;

    cudaFuncSetAttribute(dconv_main,
                         cudaFuncAttributeMaxDynamicSharedMemorySize, SMEM_TOTAL);

    prep_w<<<(O_ * C_ * KK + 255) / 256, 256>>>(weight);
    prep_x4<<<(B_ * C_ * HW_ + 255) / 256, 256>>>(x);
    dconv_main<<<B_ * H_, 384, SMEM_TOTAL>>>(offset, bias, out);
}

// round 9
// speedup vs baseline: 1.1185x; 1.1185x over previous
#include <cuda_runtime.h>
#include <cuda_bf16.h>

#define B_   4
#define C_   64
#define O_   64
#define H_   128
#define W_   128
#define KK   9
#define HW_  (H_ * W_)

// ---------------- device scratch (allocation-free rule) ----------------
__device__ float4 g_x4[B_ * C_ * HW_];   // (x[y][x], x[y][x+1], x[y+1][x], x[y+1][x+1])
__device__ uint2  g_wB[KK * 2 * 8 * 8 * 32];  // [k][plane][kt][nt][lane] -> (b0,b1)

// ---------------- prep kernels ----------------
__global__ void prep_w(const float* __restrict__ w) {
    int i = blockIdx.x * 256 + threadIdx.x;          // over O*C*KK = 36864
    if (i < O_ * C_ * KK) {
        int o = i / (C_ * KK);
        int r = i - o * (C_ * KK);
        int c = r / KK;
        int k = r - c * KK;
        float v = w[i];
        unsigned hb = __float_as_uint(v) & 0xFFFF0000u;       // bf16 truncation
        float lf = v - __uint_as_float(hb);
        unsigned h16 = hb >> 16;
        unsigned l16 = (unsigned)__bfloat16_as_ushort(__float2bfloat16(lf));
        unsigned hword = h16 | (h16 << 16);                    // (wh, wh) k-pair
        unsigned lword = l16 | (l16 << 16);                    // (wl, wl) k-pair
        int kt = c >> 3, cl = c & 7;
        int j  = cl >> 2, tg = cl & 3;
        int nt = o >> 3;
        int lane = ((o & 7) << 2) | tg;
        unsigned* bh = (unsigned*)&g_wB[(((k * 2 + 0) * 8 + kt) * 8 + nt) * 32 + lane];
        unsigned* bl = (unsigned*)&g_wB[(((k * 2 + 1) * 8 + kt) * 8 + nt) * 32 + lane];
        bh[j] = hword;
        bl[j] = lword;
    }
}

__global__ void prep_x4(const float* __restrict__ x) {
    int i = blockIdx.x * 256 + threadIdx.x;          // over B*C*HW
    if (i < B_ * C_ * HW_) {
        int col = i & (W_ - 1);
        int y   = (i >> 7) & (H_ - 1);
        float a = x[i];
        float b = (col < W_ - 1) ? x[i + 1] : a;
        float c, d;
        if (y < H_ - 1) {
            c = x[i + W_];
            d = (col < W_ - 1) ? x[i + W_ + 1] : c;
        } else { c = a; d = b; }
        g_x4[i] = make_float4(a, b, c, d);
    }
}

// ---------------- main kernel ----------------
// 512 blocks (batch*row), 384 threads: warps 0-7 producers, warps 8-11 MMA consumers.
// smem: A tiles double-buffered: [2][128 px][128 k' bf16] = 2 * 32KB
//       row = 256B = 16 units of 16B; unit u stored at u ^ (px & 7)  (XOR swizzle)
#define A_BUF_BYTES 32768
#define SMEM_TOTAL  (2 * A_BUF_BYTES)

#define BSYNC(id)   asm volatile("bar.sync %0, 384;"   :: "r"(id) : "memory")
#define BARRIVE(id) asm volatile("bar.arrive %0, 384;" :: "r"(id) : "memory")

#define LDMX4(r0, r1, r2, r3, addr)                                          \
    asm volatile("ldmatrix.sync.aligned.m8n8.x4.shared.b16 {%0,%1,%2,%3}, [%4];" \
        : "=r"(r0), "=r"(r1), "=r"(r2), "=r"(r3) : "r"(addr))

#define MMA_BF16(d, a0, a1, a2, a3, b0, b1)                                  \
    asm volatile("mma.sync.aligned.m16n8k16.row.col.f32.bf16.bf16.f32 "      \
        "{%0,%1,%2,%3}, {%4,%5,%6,%7}, {%8,%9}, {%0,%1,%2,%3};"              \
        : "+f"((d)[0]), "+f"((d)[1]), "+f"((d)[2]), "+f"((d)[3])             \
        : "r"(a0), "r"(a1), "r"(a2), "r"(a3), "r"(b0), "r"(b1))

__global__ __launch_bounds__(384, 1)
void dconv_main(const float* __restrict__ offset,
                const float* __restrict__ bias,
                float* __restrict__ out) {
    extern __shared__ char smc[];
    unsigned smb;
    asm("{ .reg .u64 t; cvta.to.shared.u64 t, %1; cvt.u32.u64 %0, t; }"
        : "=r"(smb) : "l"(smc));

    const int tid   = threadIdx.x;
    const int batch = blockIdx.x >> 7;
    const int ho    = blockIdx.x & 127;

    if (tid < 256) {
        // ================= PRODUCERS (warps 0-7) =================
        const int p     = tid & 127;         // pixel in row
        const int chalf = tid >> 7;          // channel half (32 c each)
        const float4* xb4  = g_x4 + (batch * C_ + chalf * 32) * HW_;
        const float*  offb = offset + (batch * 2 * KK) * HW_ + ho * W_ + p;

        float offy[KK], offx[KK];
        #pragma unroll
        for (int k = 0; k < KK; k++) {
            offy[k] = __ldg(offb + (2 * k) * HW_);
            offx[k] = __ldg(offb + (2 * k + 1) * HW_);
        }

        for (int k = 0; k < KK; k++) {
            const int s = k & 1;
            if (k >= 2) BSYNC(3 + s);        // wait stage empty

            // bilinear corner math (proven)
            const int ki = k / 3, kj = k - ki * 3;
            const float py  = offy[k] + (float)(ki - 1 + ho);
            const float pxx = offx[k] + (float)(kj - 1 + p);
            const float y0f = floorf(py), x0f = floorf(pxx);
            const float ly = py - y0f,  lx = pxx - x0f;
            const float hy = 1.f - ly,  hx = 1.f - lx;
            const int y0 = (int)y0f, x0 = (int)x0f;

            int ybase; float w_top, w_bot;
            if (y0 >= 0) {
                ybase = min(y0, H_ - 1);
                w_top = (y0 < H_)     ? hy : 0.f;
                w_bot = (y0 < H_ - 1) ? ly : 0.f;
            } else {
                ybase = 0;
                w_top = (y0 == -1) ? ly : 0.f;
                w_bot = 0.f;
            }
            float wa, wb;
            if (x0 >= 0 && x0 < W_) { wa = hx; wb = (x0 < W_ - 1) ? lx : 0.f; }
            else if (x0 == -1)      { wa = lx; wb = 0.f; }
            else                    { wa = 0.f; wb = 0.f; }
            const int bx = min(max(x0, 0), W_ - 1);

            const float u0 = w_top * wa, u1 = w_top * wb;
            const float u2 = w_bot * wa, u3 = w_bot * wb;

            const float4* q = xb4 + ybase * W_ + bx;
            const unsigned Arow = smb + (unsigned)s * A_BUF_BYTES + (unsigned)(p * 256);
            const unsigned sw3  = (unsigned)(p & 7);

            // 2 batches of 16 front-issued gathers (MLP=16), then convert + 4 STS.128
            #pragma unroll
            for (int half = 0; half < 2; half++) {
                float4 t[16];
                #pragma unroll
                for (int cc = 0; cc < 16; cc++)
                    t[cc] = __ldg(q + (half * 16 + cc) * HW_);

                unsigned wbuf[16];
                #pragma unroll
                for (int cc = 0; cc < 16; cc++) {
                    const float v = u0 * t[cc].x + u1 * t[cc].y
                                  + u2 * t[cc].z + u3 * t[cc].w;
                    const unsigned hb = __float_as_uint(v) & 0xFFFF0000u;
                    const float lf = v - __uint_as_float(hb);
                    const unsigned l16 =
                        (unsigned)__bfloat16_as_ushort(__float2bfloat16(lf));
                    wbuf[cc] = (hb >> 16) | (l16 << 16);   // (vh, vl) k'-pair
                }
                #pragma unroll
                for (int j = 0; j < 4; j++) {
                    const unsigned u = (unsigned)(chalf * 8 + half * 4 + j);
                    const unsigned addr = Arow + ((u ^ sw3) << 4);
                    asm volatile("st.shared.v4.b32 [%0], {%1,%2,%3,%4};"
                        :: "r"(addr), "r"(wbuf[4 * j]), "r"(wbuf[4 * j + 1]),
                           "r"(wbuf[4 * j + 2]), "r"(wbuf[4 * j + 3]));
                }
            }

            BARRIVE(1 + s);                  // stage full
        }
    } else {
        // ================= CONSUMERS (warps 8-11) =================
        const int wc   = (tid >> 5) - 8;     // 0..3 -> px block of 32
        const int lane = tid & 31;
        const int pxl  = lane & 15;          // ldmatrix row within 16
        const int usel = lane >> 4;          // ldmatrix k-unit select

        float acc[2][8][4];
        #pragma unroll
        for (int mt = 0; mt < 2; mt++)
            #pragma unroll
            for (int nt = 0; nt < 8; nt++)
                #pragma unroll
                for (int q = 0; q < 4; q++) acc[mt][nt][q] = 0.f;

        for (int k = 0; k < KK; k++) {
            const int s = k & 1;
            BSYNC(1 + s);                    // wait stage full

            const unsigned Abase = smb + (unsigned)s * A_BUF_BYTES;
            const uint2* wB = g_wB + k * 4096 + lane;

            // preload kt=0 B-fragments into buffer 0
            uint2 bh[2][8], bl[2][8];
            #pragma unroll
            for (int nt = 0; nt < 8; nt++) {
                bh[0][nt] = __ldg(wB + ((0 * 8 + 0) * 8 + nt) * 32);
                bl[0][nt] = __ldg(wB + ((1 * 8 + 0) * 8 + nt) * 32);
            }

            #pragma unroll
            for (int kt = 0; kt < 8; kt++) {
                const int cur = kt & 1, nxt = cur ^ 1;

                // A fragments for this kt (both 16-px halves)
                unsigned a[2][4];
                #pragma unroll
                for (int mt = 0; mt < 2; mt++) {
                    const int px_l = wc * 32 + mt * 16 + pxl;
                    const unsigned u = (unsigned)(2 * kt + usel);
                    const unsigned addr = Abase + (unsigned)(px_l * 256)
                                        + ((u ^ (unsigned)(px_l & 7)) << 4);
                    LDMX4(a[mt][0], a[mt][1], a[mt][2], a[mt][3], addr);
                }

                // prefetch kt+1 B-fragments (hidden under the 32 MMAs below)
                if (kt < 7) {
                    #pragma unroll
                    for (int nt = 0; nt < 8; nt++) {
                        bh[nxt][nt] = __ldg(wB + ((0 * 8 + kt + 1) * 8 + nt) * 32);
                        bl[nxt][nt] = __ldg(wB + ((1 * 8 + kt + 1) * 8 + nt) * 32);
                    }
                }

                // plane-h for all (mt,nt), then plane-l: max acc-reuse distance
                #pragma unroll
                for (int nt = 0; nt < 8; nt++) {
                    MMA_BF16(acc[0][nt], a[0][0], a[0][1], a[0][2], a[0][3],
                             bh[cur][nt].x, bh[cur][nt].y);
                    MMA_BF16(acc[1][nt], a[1][0], a[1][1], a[1][2], a[1][3],
                             bh[cur][nt].x, bh[cur][nt].y);
                }
                #pragma unroll
                for (int nt = 0; nt < 8; nt++) {
                    MMA_BF16(acc[0][nt], a[0][0], a[0][1], a[0][2], a[0][3],
                             bl[cur][nt].x, bl[cur][nt].y);
                    MMA_BF16(acc[1][nt], a[1][0], a[1][1], a[1][2], a[1][3],
                             bl[cur][nt].x, bl[cur][nt].y);
                }
            }

            BARRIVE(3 + s);                  // stage empty
        }

        // ---------------- epilogue ----------------
        const int g = lane >> 2, tg = lane & 3;
        #pragma unroll
        for (int nt = 0; nt < 8; nt++) {
            const int o = nt * 8 + 2 * tg;
            const float b0 = __ldg(bias + o);
            const float b1 = __ldg(bias + o + 1);
            float* o0 = out + (batch * O_ + o) * HW_ + ho * W_;
            float* o1 = o0 + HW_;
            #pragma unroll
            for (int mt = 0; mt < 2; mt++) {
                const int wo = wc * 32 + mt * 16 + g;
                o0[wo]     = acc[mt][nt][0] + b0;
                o1[wo]     = acc[mt][nt][1] + b1;
                o0[wo + 8] = acc[mt][nt][2] + b0;
                o1[wo + 8] = acc[mt][nt][3] + b1;
            }
        }
    }
}

extern "C" void kernel_launch(void* const* d_in, const int* in_sizes, int n_in,
                              void* d_out, int out_size) {
    const float* x      = (const float*)d_in[0];
    const float* offset = (const float*)d_in[1];
    const float* weight = (const float*)d_in[2];
    const float* bias   = (const float*)d_in[3];
    float* out = (float*)d_out;

    cudaFuncSetAttribute(dconv_main,
                         cudaFuncAttributeMaxDynamicSharedMemorySize, SMEM_TOTAL);

    prep_w<<<(O_ * C_ * KK + 255) / 256, 256>>>(weight);
    prep_x4<<<(B_ * C_ * HW_ + 255) / 256, 256>>>(x);
    dconv_main<<<B_ * H_, 384, SMEM_TOTAL>>>(offset, bias, out);
}

// round 10
// speedup vs baseline: 1.2754x; 1.1404x over previous
#include <cuda_runtime.h>
#include <cuda_bf16.h>

#define B_   4
#define C_   64
#define O_   64
#define H_   128
#define W_   128
#define KK   9
#define HW_  (H_ * W_)

// ---------------- device scratch (allocation-free rule) ----------------
__device__ float4 g_x4[B_ * C_ * HW_];   // (x[y][x], x[y][x+1], x[y+1][x], x[y+1][x+1])
__device__ uint2  g_wB[KK * 2 * 8 * 8 * 32];  // [k][plane][kt][nt][lane] -> (b0,b1)

// ---------------- prep kernels ----------------
__global__ void prep_w(const float* __restrict__ w) {
    int i = blockIdx.x * 256 + threadIdx.x;          // over O*C*KK = 36864
    if (i < O_ * C_ * KK) {
        int o = i / (C_ * KK);
        int r = i - o * (C_ * KK);
        int c = r / KK;
        int k = r - c * KK;
        float v = w[i];
        unsigned hb = __float_as_uint(v) & 0xFFFF0000u;       // bf16 truncation
        float lf = v - __uint_as_float(hb);
        unsigned h16 = hb >> 16;
        unsigned l16 = (unsigned)__bfloat16_as_ushort(__float2bfloat16(lf));
        unsigned hword = h16 | (h16 << 16);                    // (wh, wh) k-pair
        unsigned lword = l16 | (l16 << 16);                    // (wl, wl) k-pair
        int kt = c >> 3, cl = c & 7;
        int j  = cl >> 2, tg = cl & 3;
        int nt = o >> 3;
        int lane = ((o & 7) << 2) | tg;
        unsigned* bh = (unsigned*)&g_wB[(((k * 2 + 0) * 8 + kt) * 8 + nt) * 32 + lane];
        unsigned* bl = (unsigned*)&g_wB[(((k * 2 + 1) * 8 + kt) * 8 + nt) * 32 + lane];
        bh[j] = hword;
        bl[j] = lword;
    }
}

__global__ void prep_x4(const float* __restrict__ x) {
    int i = blockIdx.x * 256 + threadIdx.x;          // over B*C*HW
    if (i < B_ * C_ * HW_) {
        int col = i & (W_ - 1);
        int y   = (i >> 7) & (H_ - 1);
        float a = x[i];
        float b = (col < W_ - 1) ? x[i + 1] : a;
        float c, d;
        if (y < H_ - 1) {
            c = x[i + W_];
            d = (col < W_ - 1) ? x[i + W_ + 1] : c;
        } else { c = a; d = b; }
        g_x4[i] = make_float4(a, b, c, d);
    }
}

// ---------------- main kernel ----------------
// 512 blocks (batch*row), 512 threads:
//   warps 0-7 producers; warps 8-15 consumers (warp = 32-px block x 32-o half)
// smem: A tiles double-buffered: [2][128 px][128 k' bf16] = 2 * 32KB
//       row = 256B = 16 units of 16B; unit u stored at u ^ (px & 7)  (XOR swizzle)
#define A_BUF_BYTES 32768
#define SMEM_TOTAL  (2 * A_BUF_BYTES)

#define BSYNC(id)   asm volatile("bar.sync %0, 512;"   :: "r"(id) : "memory")
#define BARRIVE(id) asm volatile("bar.arrive %0, 512;" :: "r"(id) : "memory")

#define LDMX4(r0, r1, r2, r3, addr)                                          \
    asm volatile("ldmatrix.sync.aligned.m8n8.x4.shared.b16 {%0,%1,%2,%3}, [%4];" \
        : "=r"(r0), "=r"(r1), "=r"(r2), "=r"(r3) : "r"(addr))

#define MMA_BF16(d, a0, a1, a2, a3, b0, b1)                                  \
    asm volatile("mma.sync.aligned.m16n8k16.row.col.f32.bf16.bf16.f32 "      \
        "{%0,%1,%2,%3}, {%4,%5,%6,%7}, {%8,%9}, {%0,%1,%2,%3};"              \
        : "+f"((d)[0]), "+f"((d)[1]), "+f"((d)[2]), "+f"((d)[3])             \
        : "r"(a0), "r"(a1), "r"(a2), "r"(a3), "r"(b0), "r"(b1))

__global__ __launch_bounds__(512, 1)
void dconv_main(const float* __restrict__ offset,
                const float* __restrict__ bias,
                float* __restrict__ out) {
    extern __shared__ char smc[];
    unsigned smb;
    asm("{ .reg .u64 t; cvta.to.shared.u64 t, %1; cvt.u32.u64 %0, t; }"
        : "=r"(smb) : "l"(smc));

    const int tid   = threadIdx.x;
    const int batch = blockIdx.x >> 7;
    const int ho    = blockIdx.x & 127;

    if (tid < 256) {
        // ================= PRODUCERS (warps 0-7) =================
        const int p     = tid & 127;         // pixel in row
        const int chalf = tid >> 7;          // channel half (32 c each)
        const float4* xb4  = g_x4 + (batch * C_ + chalf * 32) * HW_;
        const float*  offb = offset + (batch * 2 * KK) * HW_ + ho * W_ + p;

        float offy[KK], offx[KK];
        #pragma unroll
        for (int k = 0; k < KK; k++) {
            offy[k] = __ldg(offb + (2 * k) * HW_);
            offx[k] = __ldg(offb + (2 * k + 1) * HW_);
        }

        for (int k = 0; k < KK; k++) {
            const int s = k & 1;
            if (k >= 2) BSYNC(3 + s);        // wait stage empty

            // bilinear corner math (proven)
            const int ki = k / 3, kj = k - ki * 3;
            const float py  = offy[k] + (float)(ki - 1 + ho);
            const float pxx = offx[k] + (float)(kj - 1 + p);
            const float y0f = floorf(py), x0f = floorf(pxx);
            const float ly = py - y0f,  lx = pxx - x0f;
            const float hy = 1.f - ly,  hx = 1.f - lx;
            const int y0 = (int)y0f, x0 = (int)x0f;

            int ybase; float w_top, w_bot;
            if (y0 >= 0) {
                ybase = min(y0, H_ - 1);
                w_top = (y0 < H_)     ? hy : 0.f;
                w_bot = (y0 < H_ - 1) ? ly : 0.f;
            } else {
                ybase = 0;
                w_top = (y0 == -1) ? ly : 0.f;
                w_bot = 0.f;
            }
            float wa, wb;
            if (x0 >= 0 && x0 < W_) { wa = hx; wb = (x0 < W_ - 1) ? lx : 0.f; }
            else if (x0 == -1)      { wa = lx; wb = 0.f; }
            else                    { wa = 0.f; wb = 0.f; }
            const int bx = min(max(x0, 0), W_ - 1);

            const float u0 = w_top * wa, u1 = w_top * wb;
            const float u2 = w_bot * wa, u3 = w_bot * wb;

            const float4* q = xb4 + ybase * W_ + bx;
            const unsigned Arow = smb + (unsigned)s * A_BUF_BYTES + (unsigned)(p * 256);
            const unsigned sw3  = (unsigned)(p & 7);

            // 2 batches of 16 front-issued gathers (MLP=16), then convert + 4 STS.128
            #pragma unroll
            for (int half = 0; half < 2; half++) {
                float4 t[16];
                #pragma unroll
                for (int cc = 0; cc < 16; cc++)
                    t[cc] = __ldg(q + (half * 16 + cc) * HW_);

                unsigned wbuf[16];
                #pragma unroll
                for (int cc = 0; cc < 16; cc++) {
                    const float v = u0 * t[cc].x + u1 * t[cc].y
                                  + u2 * t[cc].z + u3 * t[cc].w;
                    const unsigned hb = __float_as_uint(v) & 0xFFFF0000u;
                    const float lf = v - __uint_as_float(hb);
                    const unsigned l16 =
                        (unsigned)__bfloat16_as_ushort(__float2bfloat16(lf));
                    wbuf[cc] = (hb >> 16) | (l16 << 16);   // (vh, vl) k'-pair
                }
                #pragma unroll
                for (int j = 0; j < 4; j++) {
                    const unsigned u = (unsigned)(chalf * 8 + half * 4 + j);
                    const unsigned addr = Arow + ((u ^ sw3) << 4);
                    asm volatile("st.shared.v4.b32 [%0], {%1,%2,%3,%4};"
                        :: "r"(addr), "r"(wbuf[4 * j]), "r"(wbuf[4 * j + 1]),
                           "r"(wbuf[4 * j + 2]), "r"(wbuf[4 * j + 3]));
                }
            }

            BARRIVE(1 + s);                  // stage full
        }
    } else {
        // ================= CONSUMERS (warps 8-15) =================
        // warp = (pxb: 32-px block, oh: 32-o half); per kt: 2 LDSM + 8 B-lds + 16 MMA
        const int wc   = (tid >> 5) - 8;     // 0..7
        const int pxb  = wc & 3;
        const int oh   = wc >> 2;
        const int lane = tid & 31;
        const int pxl  = lane & 15;
        const int usel = lane >> 4;

        float acc[2][4][4];                  // [mt][nt][quad]
        #pragma unroll
        for (int mt = 0; mt < 2; mt++)
            #pragma unroll
            for (int nt = 0; nt < 4; nt++)
                #pragma unroll
                for (int q = 0; q < 4; q++) acc[mt][nt][q] = 0.f;

        for (int k = 0; k < KK; k++) {
            const int s = k & 1;
            BSYNC(1 + s);                    // wait stage full

            const unsigned Abase = smb + (unsigned)s * A_BUF_BYTES;
            const uint2* wB = g_wB + k * 4096 + (oh * 4 * 32) + lane;

            #pragma unroll
            for (int kt = 0; kt < 8; kt++) {
                // front-issue this kt's 8 B-fragments (uint2 LDG, L1-hot)
                uint2 bh[4], bl[4];
                #pragma unroll
                for (int nt = 0; nt < 4; nt++) {
                    bh[nt] = __ldg(wB + (0 * 64 + kt * 8 + nt) * 32);
                    bl[nt] = __ldg(wB + (1 * 64 + kt * 8 + nt) * 32);
                }

                unsigned a[2][4];
                #pragma unroll
                for (int mt = 0; mt < 2; mt++) {
                    const int px_l = pxb * 32 + mt * 16 + pxl;
                    const unsigned u = (unsigned)(2 * kt + usel);
                    const unsigned addr = Abase + (unsigned)(px_l * 256)
                                        + ((u ^ (unsigned)(px_l & 7)) << 4);
                    LDMX4(a[mt][0], a[mt][1], a[mt][2], a[mt][3], addr);
                }

                #pragma unroll
                for (int nt = 0; nt < 4; nt++) {
                    MMA_BF16(acc[0][nt], a[0][0], a[0][1], a[0][2], a[0][3],
                             bh[nt].x, bh[nt].y);
                    MMA_BF16(acc[1][nt], a[1][0], a[1][1], a[1][2], a[1][3],
                             bh[nt].x, bh[nt].y);
                }
                #pragma unroll
                for (int nt = 0; nt < 4; nt++) {
                    MMA_BF16(acc[0][nt], a[0][0], a[0][1], a[0][2], a[0][3],
                             bl[nt].x, bl[nt].y);
                    MMA_BF16(acc[1][nt], a[1][0], a[1][1], a[1][2], a[1][3],
                             bl[nt].x, bl[nt].y);
                }
            }

            BARRIVE(3 + s);                  // stage empty
        }

        // ---------------- epilogue ----------------
        const int g = lane >> 2, tg = lane & 3;
        #pragma unroll
        for (int nt = 0; nt < 4; nt++) {
            const int o = oh * 32 + nt * 8 + 2 * tg;
            const float b0 = __ldg(bias + o);
            const float b1 = __ldg(bias + o + 1);
            float* o0 = out + (batch * O_ + o) * HW_ + ho * W_;
            float* o1 = o0 + HW_;
            #pragma unroll
            for (int mt = 0; mt < 2; mt++) {
                const int wo = pxb * 32 + mt * 16 + g;
                o0[wo]     = acc[mt][nt][0] + b0;
                o1[wo]     = acc[mt][nt][1] + b1;
                o0[wo + 8] = acc[mt][nt][2] + b0;
                o1[wo + 8] = acc[mt][nt][3] + b1;
            }
        }
    }
}

extern "C" void kernel_launch(void* const* d_in, const int* in_sizes, int n_in,
                              void* d_out, int out_size) {
    const float* x      = (const float*)d_in[0];
    const float* offset = (const float*)d_in[1];
    const float* weight = (const float*)d_in[2];
    const float* bias   = (const float*)d_in[3];
    float* out = (float*)d_out;

    cudaFuncSetAttribute(dconv_main,
                         cudaFuncAttributeMaxDynamicSharedMemorySize, SMEM_TOTAL);

    prep_w<<<(O_ * C_ * KK + 255) / 256, 256>>>(weight);
    prep_x4<<<(B_ * C_ * HW_ + 255) / 256, 256>>>(x);
    dconv_main<<<B_ * H_, 512, SMEM_TOTAL>>>(offset, bias, out);
}